// round 10
// baseline (speedup 1.0000x reference)
#include <cuda_runtime.h>
#include <cuda_bf16.h>
#include <cstdint>

#define BB 4
#define CC 128
#define CO 64
#define NN 4096
#define TQ 128
#define TMT 64
#define NSTEP (NN / TMT)

// ---------------- scratch (device globals) ----------------------------------
__device__ __align__(16) __nv_bfloat16 QhG[BB * NN * CO];
__device__ __align__(16) __nv_bfloat16 QlG[BB * NN * CO];
__device__ __align__(16) __nv_bfloat16 KhG[BB * NN * CO];
__device__ __align__(16) __nv_bfloat16 KlG[BB * NN * CO];
__device__ __align__(16) __nv_bfloat16 VhG[BB * NN * CO];   // token-major [b][m][o]
__device__ __align__(16) __nv_bfloat16 VlG[BB * NN * CO];
__device__ float OdG[BB * CO * NN];

// ---------------- helpers ----------------------------------------------------
__device__ __forceinline__ uint32_t smem_u32(const void* p) {
    uint32_t a;
    asm("{ .reg .u64 t; cvta.to.shared.u64 t, %1; cvt.u32.u64 %0, t; }"
        : "=r"(a) : "l"(p));
    return a;
}
__device__ __forceinline__ float ex2f(float x) {
    float y; asm("ex2.approx.f32 %0, %1;" : "=f"(y) : "f"(x)); return y;
}
#define SWZ128(off) ((off) ^ (((off) >> 3) & 0x70))

#define LDSM_X4(r0,r1,r2,r3,addr) \
    asm volatile("ldmatrix.sync.aligned.m8n8.x4.shared.b16 {%0,%1,%2,%3}, [%4];" \
        : "=r"(r0),"=r"(r1),"=r"(r2),"=r"(r3) : "r"(addr))
#define LDSM_X4T(r0,r1,r2,r3,addr) \
    asm volatile("ldmatrix.sync.aligned.m8n8.x4.trans.shared.b16 {%0,%1,%2,%3}, [%4];" \
        : "=r"(r0),"=r"(r1),"=r"(r2),"=r"(r3) : "r"(addr))

#define MMA16816(c0,c1,c2,c3,a0,a1,a2,a3,b0,b1) \
    asm volatile("mma.sync.aligned.m16n8k16.row.col.f32.bf16.bf16.f32 " \
        "{%0,%1,%2,%3}, {%4,%5,%6,%7}, {%8,%9}, {%0,%1,%2,%3};" \
        : "+f"(c0),"+f"(c1),"+f"(c2),"+f"(c3) \
        : "r"(a0),"r"(a1),"r"(a2),"r"(a3),"r"(b0),"r"(b1))

__device__ __forceinline__ void cpa16(uint32_t dst, const void* src) {
    asm volatile("cp.async.cg.shared.global [%0], [%1], 16;" :: "r"(dst), "l"(src));
}
#define CP_COMMIT() asm volatile("cp.async.commit_group;" ::: "memory")
#define CP_WAIT(n)  asm volatile("cp.async.wait_group %0;" :: "n"(n) : "memory")

__device__ __forceinline__ uint32_t pack_bf16(float lo, float hi) {
    uint32_t r;
    asm("cvt.rn.bf16x2.f32 %0, %1, %2;" : "=r"(r) : "f"(hi), "f"(lo));
    return r;
}

// 64 rows x 64 bf16 (8KB) -> smem SW128, 128 threads, 4 cp.async each
__device__ __forceinline__ void load_arr64(uint32_t dst, const __nv_bfloat16* src, int tid) {
#pragma unroll
    for (int it = 0; it < 4; it++) {
        int i = tid + it * 128;
        int row = i >> 3, ch = i & 7;
        cpa16(dst + SWZ128((uint32_t)(row * 128 + ch * 16)),
              src + (size_t)row * CO + ch * 8);
    }
}

// ---------------------------------------------------------------------------
// Projection(s) + split-bf16 store (R4-proven).  nsets=1 (Q) or 2 (K, V).
// ---------------------------------------------------------------------------
__global__ void __launch_bounds__(256) proj2_kernel(
    const float* __restrict__ x,
    const float* __restrict__ w0, const float* __restrict__ b0, float scale0,
    __nv_bfloat16* __restrict__ hi0, __nv_bfloat16* __restrict__ lo0,
    const float* __restrict__ w1, const float* __restrict__ b1, float scale1,
    __nv_bfloat16* __restrict__ hi1, __nv_bfloat16* __restrict__ lo1,
    int nsets)
{
    extern __shared__ float sm[];
    float* Xs  = sm;                    // 8192
    float* Ws  = sm + 8192;             // 8192
    float* stgH = sm + 16384;           // 2048
    float* stgL = sm + 18432;           // 2048

    int b  = blockIdx.y;
    int n0 = blockIdx.x * 64;
    int tid = threadIdx.x;

    const float* xb = x + (size_t)b * CC * NN + n0;
    for (int i = tid; i < 2048; i += 256) {
        int c = i >> 4, j4 = (i & 15) * 4;
        *(float4*)&Xs[c * 64 + j4] = *(const float4*)&xb[(size_t)c * NN + j4];
    }

    int nx = (tid & 15) * 4;
    int og = tid >> 4;

    for (int s = 0; s < nsets; s++) {
        const float* w   = s ? w1 : w0;
        const float* bia = s ? b1 : b0;
        float scale      = s ? scale1 : scale0;
        __nv_bfloat16* hi = s ? hi1 : hi0;
        __nv_bfloat16* lo = s ? lo1 : lo0;

        __syncthreads();
        for (int i = tid; i < 2048; i += 256)
            *(float4*)&Ws[i * 4] = *(const float4*)&w[i * 4];
        __syncthreads();

        float acc[4][4];
#pragma unroll
        for (int i = 0; i < 4; i++)
#pragma unroll
            for (int j = 0; j < 4; j++) acc[i][j] = 0.f;

#pragma unroll 4
        for (int c = 0; c < CC; c += 2) {
            float4 xa = *(const float4*)&Xs[c * 64 + nx];
            float4 xb2 = *(const float4*)&Xs[(c + 1) * 64 + nx];
#pragma unroll
            for (int oi = 0; oi < 4; oi++) {
                float2 w2 = *(const float2*)&Ws[(og * 4 + oi) * CC + c];
                acc[oi][0] += w2.x * xa.x + w2.y * xb2.x;
                acc[oi][1] += w2.x * xa.y + w2.y * xb2.y;
                acc[oi][2] += w2.x * xa.z + w2.y * xb2.z;
                acc[oi][3] += w2.x * xa.w + w2.y * xb2.w;
            }
        }

        float bb[4];
#pragma unroll
        for (int oi = 0; oi < 4; oi++) bb[oi] = bia[og * 4 + oi];

#pragma unroll
        for (int j = 0; j < 4; j++) {
            float v0 = (acc[0][j] + bb[0]) * scale;
            float v1 = (acc[1][j] + bb[1]) * scale;
            float v2 = (acc[2][j] + bb[2]) * scale;
            float v3 = (acc[3][j] + bb[3]) * scale;
            uint32_t h01 = pack_bf16(v0, v1), h23 = pack_bf16(v2, v3);
            float l0 = v0 - __uint_as_float(h01 << 16);
            float l1 = v1 - __uint_as_float(h01 & 0xFFFF0000u);
            float l2 = v2 - __uint_as_float(h23 << 16);
            float l3 = v3 - __uint_as_float(h23 & 0xFFFF0000u);
            int fo = (nx + j) * 32 + og * 2;
            stgH[fo] = __uint_as_float(h01); stgH[fo + 1] = __uint_as_float(h23);
            uint32_t q01 = pack_bf16(l0, l1), q23 = pack_bf16(l2, l3);
            stgL[fo] = __uint_as_float(q01); stgL[fo + 1] = __uint_as_float(q23);
        }
        __syncthreads();

        uint4* dH = (uint4*)(hi + ((size_t)b * NN + n0) * CO);
        uint4* dL = (uint4*)(lo + ((size_t)b * NN + n0) * CO);
        for (int i = tid; i < 512; i += 256) {
            dH[i] = ((uint4*)stgH)[i];
            dL[i] = ((uint4*)stgL)[i];
        }
    }
}

// ---------------------------------------------------------------------------
// FA2 attention: TQ=128, 4 warps x 32 q-rows (2 row-blocks of 16 per warp).
// K/V fragments loaded once per warp, reused by both row-blocks; QK uses 3
// independent accumulator chains per row-block to keep the tensor pipe at rt.
// stage (32KB): Kh 8K | Kl 8K | Vh 8K | Vl 8K ; double buffered = 64KB
// ---------------------------------------------------------------------------
#define STG_BYTES 32768
#define SMEM_ATTN (2 * STG_BYTES)

__global__ void __launch_bounds__(128, 1) attn_mma_kernel(float* __restrict__ Od)
{
    extern __shared__ char smem[];
    const uint32_t sb = smem_u32(smem);

    int tid  = threadIdx.x;
    int lane = tid & 31;
    int wid  = tid >> 5;
    int b    = blockIdx.y;
    int n0   = blockIdx.x * TQ;
    int r0   = wid * 32;

    size_t kb = (size_t)b * NN * CO;

    // ---- stage Q hi/lo (128 rows x 64 bf16 = 16KB each) ----
    {
        const __nv_bfloat16* gQh = QhG + ((size_t)b * NN + n0) * CO;
        const __nv_bfloat16* gQl = QlG + ((size_t)b * NN + n0) * CO;
#pragma unroll
        for (int it = 0; it < 8; it++) {
            int i = tid + it * 128;
            int row = i >> 3, ch = i & 7;
            uint32_t off = SWZ128((uint32_t)(row * 128 + ch * 16));
            cpa16(sb + off, gQh + (size_t)row * CO + ch * 8);
            cpa16(sb + 16384 + off, gQl + (size_t)row * CO + ch * 8);
        }
    }
    CP_COMMIT();
    CP_WAIT(0);
    __syncthreads();

    uint32_t QH[2][4][4], QL[2][4][4];
#pragma unroll
    for (int rb = 0; rb < 2; rb++) {
        int rq = r0 + rb * 16 + (lane & 7) + ((lane >> 3) & 1) * 8;
        uint32_t cq = ((lane >> 4) & 1) * 16;
#pragma unroll
        for (int ks = 0; ks < 4; ks++) {
            uint32_t off = SWZ128((uint32_t)(rq * 128 + ks * 32 + cq));
            LDSM_X4(QH[rb][ks][0], QH[rb][ks][1], QH[rb][ks][2], QH[rb][ks][3], sb + off);
            LDSM_X4(QL[rb][ks][0], QL[rb][ks][1], QL[rb][ks][2], QL[rb][ks][3], sb + 16384 + off);
        }
    }
    __syncthreads();

    // ---- prologue: tile 0 into stage 0 ----
    load_arr64(sb + 0,     KhG + kb, tid);
    load_arr64(sb + 8192,  KlG + kb, tid);
    load_arr64(sb + 16384, VhG + kb, tid);
    load_arr64(sb + 24576, VlG + kb, tid);
    CP_COMMIT();

    float Oa[2][8][4];
#pragma unroll
    for (int rb = 0; rb < 2; rb++)
#pragma unroll
        for (int i = 0; i < 8; i++)
#pragma unroll
            for (int j = 0; j < 4; j++) Oa[rb][i][j] = 0.f;
    float Lr[2][2];
    Lr[0][0] = Lr[0][1] = Lr[1][0] = Lr[1][1] = 0.f;

    const int rowk = (lane & 7);
    const uint32_t cbk = ((uint32_t)(lane >> 3)) * 16;
    const int rv = (lane & 7) + ((lane >> 3) & 1) * 8;
    const uint32_t cbv = ((uint32_t)((lane >> 4) & 1)) * 16;

    for (int t = 0; t < NSTEP; t++) {
        if (t + 1 < NSTEP) {
            uint32_t db = sb + ((t + 1) & 1) * STG_BYTES;
            size_t gb = kb + (size_t)(t + 1) * TMT * CO;
            load_arr64(db + 0,     KhG + gb, tid);
            load_arr64(db + 8192,  KlG + gb, tid);
            load_arr64(db + 16384, VhG + gb, tid);
            load_arr64(db + 24576, VlG + gb, tid);
            CP_COMMIT();
            CP_WAIT(1);
        } else {
            CP_WAIT(0);
        }
        __syncthreads();

        const uint32_t kh_b = sb + (t & 1) * STG_BYTES;
        const uint32_t kl_b = kh_b + 8192;
        const uint32_t vh_b = kh_b + 16384;
        const uint32_t vl_b = kh_b + 24576;

#pragma unroll
        for (int mbp = 0; mbp < 4; mbp++) {
            uint32_t PH2[2][2][2], PL2[2][2][2];
#pragma unroll
            for (int half = 0; half < 2; half++) {
                int mb = mbp * 2 + half;
                // 3 independent accumulator chains per row-block
                float S[2][3][4];
#pragma unroll
                for (int rb = 0; rb < 2; rb++)
#pragma unroll
                    for (int cc = 0; cc < 3; cc++)
#pragma unroll
                        for (int j = 0; j < 4; j++) S[rb][cc][j] = 0.f;

#pragma unroll
                for (int kc = 0; kc < 2; kc++) {
                    uint32_t off = SWZ128((uint32_t)((mb * 8 + rowk) * 128 + kc * 64) + cbk);
                    uint32_t k0, k1, k2, k3, l0, l1, l2, l3;
                    LDSM_X4(k0, k1, k2, k3, kh_b + off);
                    LDSM_X4(l0, l1, l2, l3, kl_b + off);
#pragma unroll
                    for (int rb = 0; rb < 2; rb++) {
                        MMA16816(S[rb][0][0],S[rb][0][1],S[rb][0][2],S[rb][0][3],
                                 QH[rb][2*kc][0],QH[rb][2*kc][1],QH[rb][2*kc][2],QH[rb][2*kc][3], k0,k1);
                        MMA16816(S[rb][1][0],S[rb][1][1],S[rb][1][2],S[rb][1][3],
                                 QH[rb][2*kc][0],QH[rb][2*kc][1],QH[rb][2*kc][2],QH[rb][2*kc][3], l0,l1);
                        MMA16816(S[rb][2][0],S[rb][2][1],S[rb][2][2],S[rb][2][3],
                                 QL[rb][2*kc][0],QL[rb][2*kc][1],QL[rb][2*kc][2],QL[rb][2*kc][3], k0,k1);
                        MMA16816(S[rb][0][0],S[rb][0][1],S[rb][0][2],S[rb][0][3],
                                 QH[rb][2*kc+1][0],QH[rb][2*kc+1][1],QH[rb][2*kc+1][2],QH[rb][2*kc+1][3], k2,k3);
                        MMA16816(S[rb][1][0],S[rb][1][1],S[rb][1][2],S[rb][1][3],
                                 QH[rb][2*kc+1][0],QH[rb][2*kc+1][1],QH[rb][2*kc+1][2],QH[rb][2*kc+1][3], l2,l3);
                        MMA16816(S[rb][2][0],S[rb][2][1],S[rb][2][2],S[rb][2][3],
                                 QL[rb][2*kc+1][0],QL[rb][2*kc+1][1],QL[rb][2*kc+1][2],QL[rb][2*kc+1][3], k2,k3);
                    }
                }

#pragma unroll
                for (int rb = 0; rb < 2; rb++) {
                    float c0 = S[rb][0][0] + S[rb][1][0] + S[rb][2][0];
                    float c1 = S[rb][0][1] + S[rb][1][1] + S[rb][2][1];
                    float c2 = S[rb][0][2] + S[rb][1][2] + S[rb][2][2];
                    float c3 = S[rb][0][3] + S[rb][1][3] + S[rb][2][3];
                    float p0 = ex2f(c0), p1 = ex2f(c1), p2 = ex2f(c2), p3 = ex2f(c3);
                    Lr[rb][0] += p0 + p1;
                    Lr[rb][1] += p2 + p3;
                    uint32_t h01 = pack_bf16(p0, p1);
                    uint32_t h23 = pack_bf16(p2, p3);
                    float l0 = p0 - __uint_as_float(h01 << 16);
                    float l1 = p1 - __uint_as_float(h01 & 0xFFFF0000u);
                    float l2 = p2 - __uint_as_float(h23 << 16);
                    float l3 = p3 - __uint_as_float(h23 & 0xFFFF0000u);
                    PH2[rb][half][0] = h01; PH2[rb][half][1] = h23;
                    PL2[rb][half][0] = pack_bf16(l0, l1);
                    PL2[rb][half][1] = pack_bf16(l2, l3);
                }
            }

            // PV: V fragments loaded once, used by both row-blocks
#pragma unroll
            for (int oc = 0; oc < 4; oc++) {
                uint32_t off = SWZ128((uint32_t)((mbp * 16 + rv) * 128 + oc * 32) + cbv);
                uint32_t v0, v1, v2, v3;
                LDSM_X4T(v0, v1, v2, v3, vh_b + off);
#pragma unroll
                for (int rb = 0; rb < 2; rb++) {
                    MMA16816(Oa[rb][2*oc][0],Oa[rb][2*oc][1],Oa[rb][2*oc][2],Oa[rb][2*oc][3],
                             PH2[rb][0][0],PH2[rb][0][1],PH2[rb][1][0],PH2[rb][1][1], v0,v1);
                    MMA16816(Oa[rb][2*oc+1][0],Oa[rb][2*oc+1][1],Oa[rb][2*oc+1][2],Oa[rb][2*oc+1][3],
                             PH2[rb][0][0],PH2[rb][0][1],PH2[rb][1][0],PH2[rb][1][1], v2,v3);
                    MMA16816(Oa[rb][2*oc][0],Oa[rb][2*oc][1],Oa[rb][2*oc][2],Oa[rb][2*oc][3],
                             PL2[rb][0][0],PL2[rb][0][1],PL2[rb][1][0],PL2[rb][1][1], v0,v1);
                    MMA16816(Oa[rb][2*oc+1][0],Oa[rb][2*oc+1][1],Oa[rb][2*oc+1][2],Oa[rb][2*oc+1][3],
                             PL2[rb][0][0],PL2[rb][0][1],PL2[rb][1][0],PL2[rb][1][1], v2,v3);
                }
                LDSM_X4T(v0, v1, v2, v3, vl_b + off);
#pragma unroll
                for (int rb = 0; rb < 2; rb++) {
                    MMA16816(Oa[rb][2*oc][0],Oa[rb][2*oc][1],Oa[rb][2*oc][2],Oa[rb][2*oc][3],
                             PH2[rb][0][0],PH2[rb][0][1],PH2[rb][1][0],PH2[rb][1][1], v0,v1);
                    MMA16816(Oa[rb][2*oc+1][0],Oa[rb][2*oc+1][1],Oa[rb][2*oc+1][2],Oa[rb][2*oc+1][3],
                             PH2[rb][0][0],PH2[rb][0][1],PH2[rb][1][0],PH2[rb][1][1], v2,v3);
                }
            }
        }
        __syncthreads();
    }

    // ---- quad-reduce L, normalize, stage [64 o][128 r], store ----
#pragma unroll
    for (int rb = 0; rb < 2; rb++) {
#pragma unroll
        for (int h = 0; h < 2; h++) {
            Lr[rb][h] += __shfl_xor_sync(0xffffffffu, Lr[rb][h], 1);
            Lr[rb][h] += __shfl_xor_sync(0xffffffffu, Lr[rb][h], 2);
        }
    }

    float* stg = (float*)smem;    // [64 o][132] = 33792B
    int g = lane >> 2, u = lane & 3;
#pragma unroll
    for (int rb = 0; rb < 2; rb++) {
        int rA = r0 + rb * 16 + g;
        int rB = rA + 8;
        float invA = 1.f / Lr[rb][0];
        float invB = 1.f / Lr[rb][1];
#pragma unroll
        for (int ob = 0; ob < 8; ob++) {
            int o0 = ob * 8 + 2 * u;
            stg[o0 * 132 + rA]       = Oa[rb][ob][0] * invA;
            stg[(o0 + 1) * 132 + rA] = Oa[rb][ob][1] * invA;
            stg[o0 * 132 + rB]       = Oa[rb][ob][2] * invB;
            stg[(o0 + 1) * 132 + rB] = Oa[rb][ob][3] * invB;
        }
    }
    __syncthreads();
    for (int idx = tid; idx < CO * TQ; idx += 128) {
        int o = idx >> 7, r = idx & 127;
        Od[((size_t)b * CO + o) * NN + n0 + r] = stg[o * 132 + r];
    }
}

// ---------------------------------------------------------------------------
// Epilogue: y = wc @ Od + bc -> BN -> ReLU -> out = img + y.  32-wide tiles.
// ---------------------------------------------------------------------------
__global__ void __launch_bounds__(256) out_kernel(
    const float* __restrict__ img, const float* __restrict__ wc,
    const float* __restrict__ bc, const float* __restrict__ gamma,
    const float* __restrict__ beta, const float* __restrict__ mean,
    const float* __restrict__ var, float* __restrict__ out)
{
    extern __shared__ float sm[];
    float* Os = sm;            // [64 o][32 n] = 2048
    float* Ws = sm + 2048;     // [128 c][64 o] = 8192

    int b  = blockIdx.y;
    int n0 = blockIdx.x * 32;
    int tid = threadIdx.x;

    const float* Ob = OdG + (size_t)b * CO * NN;
    for (int idx = tid; idx < 2048; idx += 256) {
        int o = idx >> 5, j = idx & 31;
        Os[idx] = Ob[(size_t)o * NN + n0 + j];
    }
    for (int i = tid; i < 2048; i += 256)
        *(float4*)&Ws[i * 4] = *(const float4*)&wc[i * 4];
    __syncthreads();

    int nx = (tid & 7) * 4;
    int cg = tid >> 3;
    float acc[4][4];
#pragma unroll
    for (int i = 0; i < 4; i++)
#pragma unroll
        for (int j = 0; j < 4; j++) acc[i][j] = 0.f;

#pragma unroll 4
    for (int o = 0; o < CO; o += 2) {
        float4 a0 = *(const float4*)&Os[o * 32 + nx];
        float4 a1 = *(const float4*)&Os[(o + 1) * 32 + nx];
#pragma unroll
        for (int ci = 0; ci < 4; ci++) {
            int c = cg * 4 + ci;
            float2 w2 = *(const float2*)&Ws[c * CO + o];
            acc[ci][0] += w2.x * a0.x + w2.y * a1.x;
            acc[ci][1] += w2.x * a0.y + w2.y * a1.y;
            acc[ci][2] += w2.x * a0.z + w2.y * a1.z;
            acc[ci][3] += w2.x * a0.w + w2.y * a1.w;
        }
    }

#pragma unroll
    for (int ci = 0; ci < 4; ci++) {
        int c = cg * 4 + ci;
        float inv   = gamma[c] * rsqrtf(var[c] + 1e-5f);
        float shift = beta[c] - mean[c] * inv;
        float bias  = bc[c];
        size_t base = (size_t)b * CC * NN + (size_t)c * NN + n0 + nx;
        float4 iv = *(const float4*)&img[base];
        float4 r;
        float y;
        y = (acc[ci][0] + bias) * inv + shift; r.x = iv.x + fmaxf(y, 0.f);
        y = (acc[ci][1] + bias) * inv + shift; r.y = iv.y + fmaxf(y, 0.f);
        y = (acc[ci][2] + bias) * inv + shift; r.z = iv.z + fmaxf(y, 0.f);
        y = (acc[ci][3] + bias) * inv + shift; r.w = iv.w + fmaxf(y, 0.f);
        *(float4*)&out[base] = r;
    }
}

// ---------------------------------------------------------------------------
extern "C" void kernel_launch(void* const* d_in, const int* in_sizes, int n_in,
                              void* d_out, int out_size)
{
    const float* range_x = (const float*)d_in[0];
    const float* img     = (const float*)d_in[1];
    const float* wq      = (const float*)d_in[2];
    const float* bq      = (const float*)d_in[3];
    const float* wk      = (const float*)d_in[4];
    const float* bk      = (const float*)d_in[5];
    const float* wv      = (const float*)d_in[6];
    const float* bv      = (const float*)d_in[7];
    const float* wc      = (const float*)d_in[8];
    const float* bc      = (const float*)d_in[9];
    const float* g       = (const float*)d_in[10];
    const float* be      = (const float*)d_in[11];
    const float* mn      = (const float*)d_in[12];
    const float* vr      = (const float*)d_in[13];
    float* out = (float*)d_out;

    __nv_bfloat16 *qh, *ql, *kh, *kl, *vh, *vl;
    float* od;
    cudaGetSymbolAddress((void**)&qh, QhG);
    cudaGetSymbolAddress((void**)&ql, QlG);
    cudaGetSymbolAddress((void**)&kh, KhG);
    cudaGetSymbolAddress((void**)&kl, KlG);
    cudaGetSymbolAddress((void**)&vh, VhG);
    cudaGetSymbolAddress((void**)&vl, VlG);
    cudaGetSymbolAddress((void**)&od, OdG);

    int smProj = 20480 * sizeof(float);   // 80KB
    int smOut  = 10240 * sizeof(float);   // 40KB

    cudaFuncSetAttribute(proj2_kernel, cudaFuncAttributeMaxDynamicSharedMemorySize, smProj);
    cudaFuncSetAttribute(attn_mma_kernel, cudaFuncAttributeMaxDynamicSharedMemorySize, SMEM_ATTN);
    cudaFuncSetAttribute(out_kernel, cudaFuncAttributeMaxDynamicSharedMemorySize, smOut);

    const float LOG2E = 1.4426950408889634f;
    dim3 gp(NN / 64, BB);    // 256 CTAs

    proj2_kernel<<<gp, 256, smProj>>>(range_x, wq, bq, LOG2E, qh, ql,
                                      nullptr, nullptr, 0.f, nullptr, nullptr, 1);
    proj2_kernel<<<gp, 256, smProj>>>(img, wk, bk, 1.0f, kh, kl,
                                      wv, bv, 1.0f, vh, vl, 2);

    dim3 ga(NN / TQ, BB);    // 32 x 4 = 128 CTAs, one per SM
    attn_mma_kernel<<<ga, 128, SMEM_ATTN>>>(od);

    dim3 go(NN / 32, BB);    // 512 CTAs
    out_kernel<<<go, 256, smOut>>>(img, wc, bc, g, be, mn, vr, out);
}

// round 12
// speedup vs baseline: 1.2977x; 1.2977x over previous
#include <cuda_runtime.h>
#include <cuda_bf16.h>
#include <cstdint>

#define BB 4
#define CC 128
#define CO 64
#define NN 4096
#define TQ 128
#define TMT 64
#define NSTEP (NN / TMT)

// ---------------- scratch (device globals) ----------------------------------
__device__ __align__(16) __nv_bfloat16 QhG[BB * NN * CO];
__device__ __align__(16) __nv_bfloat16 QlG[BB * NN * CO];
__device__ __align__(16) __nv_bfloat16 KhG[BB * NN * CO];
__device__ __align__(16) __nv_bfloat16 KlG[BB * NN * CO];
__device__ __align__(16) __nv_bfloat16 VhG[BB * NN * CO];   // token-major [b][m][o]
__device__ __align__(16) __nv_bfloat16 VlG[BB * NN * CO];
__device__ float OdG[BB * CO * NN];

// ---------------- helpers ----------------------------------------------------
__device__ __forceinline__ uint32_t smem_u32(const void* p) {
    uint32_t a;
    asm("{ .reg .u64 t; cvta.to.shared.u64 t, %1; cvt.u32.u64 %0, t; }"
        : "=r"(a) : "l"(p));
    return a;
}
__device__ __forceinline__ float ex2f(float x) {
    float y; asm("ex2.approx.f32 %0, %1;" : "=f"(y) : "f"(x)); return y;
}
#define SWZ128(off) ((off) ^ (((off) >> 3) & 0x70))

#define LDSM_X4(r0,r1,r2,r3,addr) \
    asm volatile("ldmatrix.sync.aligned.m8n8.x4.shared.b16 {%0,%1,%2,%3}, [%4];" \
        : "=r"(r0),"=r"(r1),"=r"(r2),"=r"(r3) : "r"(addr))
#define LDSM_X4T(r0,r1,r2,r3,addr) \
    asm volatile("ldmatrix.sync.aligned.m8n8.x4.trans.shared.b16 {%0,%1,%2,%3}, [%4];" \
        : "=r"(r0),"=r"(r1),"=r"(r2),"=r"(r3) : "r"(addr))

#define MMA16816(c0,c1,c2,c3,a0,a1,a2,a3,b0,b1) \
    asm volatile("mma.sync.aligned.m16n8k16.row.col.f32.bf16.bf16.f32 " \
        "{%0,%1,%2,%3}, {%4,%5,%6,%7}, {%8,%9}, {%0,%1,%2,%3};" \
        : "+f"(c0),"+f"(c1),"+f"(c2),"+f"(c3) \
        : "r"(a0),"r"(a1),"r"(a2),"r"(a3),"r"(b0),"r"(b1))

__device__ __forceinline__ void cpa16(uint32_t dst, const void* src) {
    asm volatile("cp.async.cg.shared.global [%0], [%1], 16;" :: "r"(dst), "l"(src));
}
#define CP_COMMIT() asm volatile("cp.async.commit_group;" ::: "memory")
#define CP_WAIT(n)  asm volatile("cp.async.wait_group %0;" :: "n"(n) : "memory")

__device__ __forceinline__ uint32_t pack_bf16(float lo, float hi) {
    uint32_t r;
    asm("cvt.rn.bf16x2.f32 %0, %1, %2;" : "=r"(r) : "f"(hi), "f"(lo));
    return r;
}

// 64 rows x 64 bf16 (8KB) -> smem SW128, 256 threads, 2 cp.async each
__device__ __forceinline__ void load_arr64_256(uint32_t dst, const __nv_bfloat16* src, int tid) {
#pragma unroll
    for (int it = 0; it < 2; it++) {
        int i = tid + it * 256;
        int row = i >> 3, ch = i & 7;
        cpa16(dst + SWZ128((uint32_t)(row * 128 + ch * 16)),
              src + (size_t)row * CO + ch * 8);
    }
}

// ---------------------------------------------------------------------------
// Q+K+V projections in ONE kernel (3 sets), split-bf16 store (R4-proven body).
// set 0: x=xq (range_x, scaled by log2 e) -> Qh/Ql
// set 1: x=xkv (img)                      -> Kh/Kl
// set 2: x=xkv (Xs kept)                  -> Vh/Vl
// ---------------------------------------------------------------------------
__global__ void __launch_bounds__(256) proj3_kernel(
    const float* __restrict__ xq, const float* __restrict__ xkv, float scaleq,
    const float* __restrict__ w0, const float* __restrict__ b0,
    __nv_bfloat16* __restrict__ hi0, __nv_bfloat16* __restrict__ lo0,
    const float* __restrict__ w1, const float* __restrict__ b1,
    __nv_bfloat16* __restrict__ hi1, __nv_bfloat16* __restrict__ lo1,
    const float* __restrict__ w2, const float* __restrict__ b2,
    __nv_bfloat16* __restrict__ hi2, __nv_bfloat16* __restrict__ lo2)
{
    extern __shared__ float sm[];
    float* Xs  = sm;                    // 8192 floats
    float* Ws  = sm + 8192;             // 2048
    float* stgH = sm + 16384;           // 2048
    float* stgL = sm + 18432;           // 2048

    int b  = blockIdx.y;
    int n0 = blockIdx.x * 64;
    int tid = threadIdx.x;

    int nx = (tid & 15) * 4;
    int og = tid >> 4;

    for (int s = 0; s < 3; s++) {
        const float* w   = s == 0 ? w0 : (s == 1 ? w1 : w2);
        const float* bia = s == 0 ? b0 : (s == 1 ? b1 : b2);
        float scale      = s == 0 ? scaleq : 1.0f;
        __nv_bfloat16* hi = s == 0 ? hi0 : (s == 1 ? hi1 : hi2);
        __nv_bfloat16* lo = s == 0 ? lo0 : (s == 1 ? lo1 : lo2);

        __syncthreads();
        if (s < 2) {
            const float* xb = (s == 0 ? xq : xkv) + (size_t)b * CC * NN + n0;
            for (int i = tid; i < 2048; i += 256) {
                int c = i >> 4, j4 = (i & 15) * 4;
                *(float4*)&Xs[c * 64 + j4] = *(const float4*)&xb[(size_t)c * NN + j4];
            }
        }
        for (int i = tid; i < 2048; i += 256)
            *(float4*)&Ws[i * 4] = *(const float4*)&w[i * 4];
        __syncthreads();

        float acc[4][4];
#pragma unroll
        for (int i = 0; i < 4; i++)
#pragma unroll
            for (int j = 0; j < 4; j++) acc[i][j] = 0.f;

#pragma unroll 4
        for (int c = 0; c < CC; c += 2) {
            float4 xa = *(const float4*)&Xs[c * 64 + nx];
            float4 xb2 = *(const float4*)&Xs[(c + 1) * 64 + nx];
#pragma unroll
            for (int oi = 0; oi < 4; oi++) {
                float2 w2v = *(const float2*)&Ws[(og * 4 + oi) * CC + c];
                acc[oi][0] += w2v.x * xa.x + w2v.y * xb2.x;
                acc[oi][1] += w2v.x * xa.y + w2v.y * xb2.y;
                acc[oi][2] += w2v.x * xa.z + w2v.y * xb2.z;
                acc[oi][3] += w2v.x * xa.w + w2v.y * xb2.w;
            }
        }

        float bb[4];
#pragma unroll
        for (int oi = 0; oi < 4; oi++) bb[oi] = bia[og * 4 + oi];

#pragma unroll
        for (int j = 0; j < 4; j++) {
            float v0 = (acc[0][j] + bb[0]) * scale;
            float v1 = (acc[1][j] + bb[1]) * scale;
            float v2 = (acc[2][j] + bb[2]) * scale;
            float v3 = (acc[3][j] + bb[3]) * scale;
            uint32_t h01 = pack_bf16(v0, v1), h23 = pack_bf16(v2, v3);
            float l0 = v0 - __uint_as_float(h01 << 16);
            float l1 = v1 - __uint_as_float(h01 & 0xFFFF0000u);
            float l2 = v2 - __uint_as_float(h23 << 16);
            float l3 = v3 - __uint_as_float(h23 & 0xFFFF0000u);
            int fo = (nx + j) * 32 + og * 2;
            stgH[fo] = __uint_as_float(h01); stgH[fo + 1] = __uint_as_float(h23);
            uint32_t q01 = pack_bf16(l0, l1), q23 = pack_bf16(l2, l3);
            stgL[fo] = __uint_as_float(q01); stgL[fo + 1] = __uint_as_float(q23);
        }
        __syncthreads();

        uint4* dH = (uint4*)(hi + ((size_t)b * NN + n0) * CO);
        uint4* dL = (uint4*)(lo + ((size_t)b * NN + n0) * CO);
        for (int i = tid; i < 512; i += 256) {
            dH[i] = ((uint4*)stgH)[i];
            dL[i] = ((uint4*)stgL)[i];
        }
    }
}

// ---------------------------------------------------------------------------
// FA2 attention: TQ=128, 256 thr = 8 warps = 4 q-groups(32 rows) x 2 m-halves.
// Each warp: 32 q-rows (2 row-blocks of 16), half the m-range of each tile.
// K/V fragments amortize over 32 rows -> smem crossbar traffic per q-row
// halved vs R4. Partial PV accums + L sums combined through smem (additive:
// unnormalized exp2 softmax, no running max).
// stage (32KB): Kh 8K | Kl 8K | Vh 8K | Vl 8K ; double buffered = 64KB
// combine: Sred[128][68] | SL[128] | Sout[64][132]  (reuses stage area)
// ---------------------------------------------------------------------------
#define STG_BYTES 32768
#define SRED_OFF 0
#define SL_OFF   34816
#define SOUT_OFF 35328
#define SMEM_ATTN 69632

__global__ void __launch_bounds__(256, 1) attn_mma_kernel(float* __restrict__ Od)
{
    extern __shared__ char smem[];
    const uint32_t sb = smem_u32(smem);

    int tid  = threadIdx.x;
    int lane = tid & 31;
    int wid  = tid >> 5;
    int qg   = wid & 3;     // q-row group (32 rows)
    int mh   = wid >> 2;    // m-half
    int b    = blockIdx.y;
    int n0   = blockIdx.x * TQ;
    int r0   = qg * 32;

    size_t kb = (size_t)b * NN * CO;

    // ---- stage Q hi/lo (128 rows x 64 bf16 = 16KB each) ----
    {
        const __nv_bfloat16* gQh = QhG + ((size_t)b * NN + n0) * CO;
        const __nv_bfloat16* gQl = QlG + ((size_t)b * NN + n0) * CO;
#pragma unroll
        for (int it = 0; it < 4; it++) {
            int i = tid + it * 256;
            int row = i >> 3, ch = i & 7;
            uint32_t off = SWZ128((uint32_t)(row * 128 + ch * 16));
            cpa16(sb + off, gQh + (size_t)row * CO + ch * 8);
            cpa16(sb + 16384 + off, gQl + (size_t)row * CO + ch * 8);
        }
    }
    CP_COMMIT();
    CP_WAIT(0);
    __syncthreads();

    uint32_t QH[2][4][4], QL[2][4][4];
#pragma unroll
    for (int rb = 0; rb < 2; rb++) {
        int rq = r0 + rb * 16 + (lane & 7) + ((lane >> 3) & 1) * 8;
        uint32_t cq = ((lane >> 4) & 1) * 16;
#pragma unroll
        for (int ks = 0; ks < 4; ks++) {
            uint32_t off = SWZ128((uint32_t)(rq * 128 + ks * 32 + cq));
            LDSM_X4(QH[rb][ks][0], QH[rb][ks][1], QH[rb][ks][2], QH[rb][ks][3], sb + off);
            LDSM_X4(QL[rb][ks][0], QL[rb][ks][1], QL[rb][ks][2], QL[rb][ks][3], sb + 16384 + off);
        }
    }
    __syncthreads();

    // ---- prologue: tile 0 into stage 0 ----
    load_arr64_256(sb + 0,     KhG + kb, tid);
    load_arr64_256(sb + 8192,  KlG + kb, tid);
    load_arr64_256(sb + 16384, VhG + kb, tid);
    load_arr64_256(sb + 24576, VlG + kb, tid);
    CP_COMMIT();

    float Oa[2][8][4];
#pragma unroll
    for (int rb = 0; rb < 2; rb++)
#pragma unroll
        for (int i = 0; i < 8; i++)
#pragma unroll
            for (int j = 0; j < 4; j++) Oa[rb][i][j] = 0.f;
    float Lr[2][2];
    Lr[0][0] = Lr[0][1] = Lr[1][0] = Lr[1][1] = 0.f;

    const int rowk = (lane & 7);
    const uint32_t cbk = ((uint32_t)(lane >> 3)) * 16;
    const int rv = (lane & 7) + ((lane >> 3) & 1) * 8;
    const uint32_t cbv = ((uint32_t)((lane >> 4) & 1)) * 16;

    for (int t = 0; t < NSTEP; t++) {
        if (t + 1 < NSTEP) {
            uint32_t db = sb + ((t + 1) & 1) * STG_BYTES;
            size_t gb = kb + (size_t)(t + 1) * TMT * CO;
            load_arr64_256(db + 0,     KhG + gb, tid);
            load_arr64_256(db + 8192,  KlG + gb, tid);
            load_arr64_256(db + 16384, VhG + gb, tid);
            load_arr64_256(db + 24576, VlG + gb, tid);
            CP_COMMIT();
            CP_WAIT(1);
        } else {
            CP_WAIT(0);
        }
        __syncthreads();

        const uint32_t kh_b = sb + (t & 1) * STG_BYTES;
        const uint32_t kl_b = kh_b + 8192;
        const uint32_t vh_b = kh_b + 16384;
        const uint32_t vl_b = kh_b + 24576;

#pragma unroll
        for (int ii = 0; ii < 2; ii++) {
            int mbp = mh * 2 + ii;          // global 16-row V block
            uint32_t PH2[2][2][2], PL2[2][2][2];
#pragma unroll
            for (int half = 0; half < 2; half++) {
                int mb = mbp * 2 + half;    // global 8-row K block
                float c0[2], c1[2], c2[2], c3[2];
#pragma unroll
                for (int rb = 0; rb < 2; rb++) { c0[rb]=0.f; c1[rb]=0.f; c2[rb]=0.f; c3[rb]=0.f; }
#pragma unroll
                for (int kc = 0; kc < 2; kc++) {
                    uint32_t off = SWZ128((uint32_t)((mb * 8 + rowk) * 128 + kc * 64) + cbk);
                    uint32_t k0, k1, k2, k3;
                    LDSM_X4(k0, k1, k2, k3, kh_b + off);
#pragma unroll
                    for (int rb = 0; rb < 2; rb++) {
                        MMA16816(c0[rb],c1[rb],c2[rb],c3[rb],
                                 QH[rb][2*kc][0],QH[rb][2*kc][1],QH[rb][2*kc][2],QH[rb][2*kc][3], k0,k1);
                        MMA16816(c0[rb],c1[rb],c2[rb],c3[rb],
                                 QH[rb][2*kc+1][0],QH[rb][2*kc+1][1],QH[rb][2*kc+1][2],QH[rb][2*kc+1][3], k2,k3);
                        MMA16816(c0[rb],c1[rb],c2[rb],c3[rb],
                                 QL[rb][2*kc][0],QL[rb][2*kc][1],QL[rb][2*kc][2],QL[rb][2*kc][3], k0,k1);
                        MMA16816(c0[rb],c1[rb],c2[rb],c3[rb],
                                 QL[rb][2*kc+1][0],QL[rb][2*kc+1][1],QL[rb][2*kc+1][2],QL[rb][2*kc+1][3], k2,k3);
                    }
                    LDSM_X4(k0, k1, k2, k3, kl_b + off);
#pragma unroll
                    for (int rb = 0; rb < 2; rb++) {
                        MMA16816(c0[rb],c1[rb],c2[rb],c3[rb],
                                 QH[rb][2*kc][0],QH[rb][2*kc][1],QH[rb][2*kc][2],QH[rb][2*kc][3], k0,k1);
                        MMA16816(c0[rb],c1[rb],c2[rb],c3[rb],
                                 QH[rb][2*kc+1][0],QH[rb][2*kc+1][1],QH[rb][2*kc+1][2],QH[rb][2*kc+1][3], k2,k3);
                    }
                }
#pragma unroll
                for (int rb = 0; rb < 2; rb++) {
                    float p0 = ex2f(c0[rb]), p1 = ex2f(c1[rb]);
                    float p2 = ex2f(c2[rb]), p3 = ex2f(c3[rb]);
                    Lr[rb][0] += p0 + p1;
                    Lr[rb][1] += p2 + p3;
                    uint32_t h01 = pack_bf16(p0, p1);
                    uint32_t h23 = pack_bf16(p2, p3);
                    float l0 = p0 - __uint_as_float(h01 << 16);
                    float l1 = p1 - __uint_as_float(h01 & 0xFFFF0000u);
                    float l2 = p2 - __uint_as_float(h23 << 16);
                    float l3 = p3 - __uint_as_float(h23 & 0xFFFF0000u);
                    PH2[rb][half][0] = h01; PH2[rb][half][1] = h23;
                    PL2[rb][half][0] = pack_bf16(l0, l1);
                    PL2[rb][half][1] = pack_bf16(l2, l3);
                }
            }

            // PV for this warp's mbp: V fragments shared by both row-blocks
#pragma unroll
            for (int oc = 0; oc < 4; oc++) {
                uint32_t off = SWZ128((uint32_t)((mbp * 16 + rv) * 128 + oc * 32) + cbv);
                uint32_t v0, v1, v2, v3;
                LDSM_X4T(v0, v1, v2, v3, vh_b + off);
#pragma unroll
                for (int rb = 0; rb < 2; rb++) {
                    MMA16816(Oa[rb][2*oc][0],Oa[rb][2*oc][1],Oa[rb][2*oc][2],Oa[rb][2*oc][3],
                             PH2[rb][0][0],PH2[rb][0][1],PH2[rb][1][0],PH2[rb][1][1], v0,v1);
                    MMA16816(Oa[rb][2*oc+1][0],Oa[rb][2*oc+1][1],Oa[rb][2*oc+1][2],Oa[rb][2*oc+1][3],
                             PH2[rb][0][0],PH2[rb][0][1],PH2[rb][1][0],PH2[rb][1][1], v2,v3);
                    MMA16816(Oa[rb][2*oc][0],Oa[rb][2*oc][1],Oa[rb][2*oc][2],Oa[rb][2*oc][3],
                             PL2[rb][0][0],PL2[rb][0][1],PL2[rb][1][0],PL2[rb][1][1], v0,v1);
                    MMA16816(Oa[rb][2*oc+1][0],Oa[rb][2*oc+1][1],Oa[rb][2*oc+1][2],Oa[rb][2*oc+1][3],
                             PL2[rb][0][0],PL2[rb][0][1],PL2[rb][1][0],PL2[rb][1][1], v2,v3);
                }
                LDSM_X4T(v0, v1, v2, v3, vl_b + off);
#pragma unroll
                for (int rb = 0; rb < 2; rb++) {
                    MMA16816(Oa[rb][2*oc][0],Oa[rb][2*oc][1],Oa[rb][2*oc][2],Oa[rb][2*oc][3],
                             PH2[rb][0][0],PH2[rb][0][1],PH2[rb][1][0],PH2[rb][1][1], v0,v1);
                    MMA16816(Oa[rb][2*oc+1][0],Oa[rb][2*oc+1][1],Oa[rb][2*oc+1][2],Oa[rb][2*oc+1][3],
                             PH2[rb][0][0],PH2[rb][0][1],PH2[rb][1][0],PH2[rb][1][1], v2,v3);
                }
            }
        }
        __syncthreads();
    }

    // ---- quad-reduce L ----
#pragma unroll
    for (int rb = 0; rb < 2; rb++)
#pragma unroll
        for (int h = 0; h < 2; h++) {
            Lr[rb][h] += __shfl_xor_sync(0xffffffffu, Lr[rb][h], 1);
            Lr[rb][h] += __shfl_xor_sync(0xffffffffu, Lr[rb][h], 2);
        }

    // ---- combine m-halves via smem, normalize, stage, store ----
    float* Sred = (float*)(smem + SRED_OFF);   // [128 r][68]
    float* SLp  = (float*)(smem + SL_OFF);     // [128]
    float* Sout = (float*)(smem + SOUT_OFF);   // [64 o][132]
    int g = lane >> 2, u = lane & 3;

    if (mh == 1) {
#pragma unroll
        for (int rb = 0; rb < 2; rb++) {
            int rA = r0 + rb * 16 + g, rB = rA + 8;
#pragma unroll
            for (int ob = 0; ob < 8; ob++) {
                int o0 = ob * 8 + 2 * u;
                Sred[rA * 68 + o0]     = Oa[rb][ob][0];
                Sred[rA * 68 + o0 + 1] = Oa[rb][ob][1];
                Sred[rB * 68 + o0]     = Oa[rb][ob][2];
                Sred[rB * 68 + o0 + 1] = Oa[rb][ob][3];
            }
            if (u == 0) { SLp[rA] = Lr[rb][0]; SLp[rB] = Lr[rb][1]; }
        }
    }
    __syncthreads();
    if (mh == 0) {
#pragma unroll
        for (int rb = 0; rb < 2; rb++) {
            int rA = r0 + rb * 16 + g, rB = rA + 8;
            float invA = 1.f / (Lr[rb][0] + SLp[rA]);
            float invB = 1.f / (Lr[rb][1] + SLp[rB]);
#pragma unroll
            for (int ob = 0; ob < 8; ob++) {
                int o0 = ob * 8 + 2 * u;
                Sout[o0 * 132 + rA]       = (Oa[rb][ob][0] + Sred[rA * 68 + o0])     * invA;
                Sout[(o0 + 1) * 132 + rA] = (Oa[rb][ob][1] + Sred[rA * 68 + o0 + 1]) * invA;
                Sout[o0 * 132 + rB]       = (Oa[rb][ob][2] + Sred[rB * 68 + o0])     * invB;
                Sout[(o0 + 1) * 132 + rB] = (Oa[rb][ob][3] + Sred[rB * 68 + o0 + 1]) * invB;
            }
        }
    }
    __syncthreads();
    for (int idx = tid; idx < CO * TQ; idx += 256) {
        int o = idx >> 7, r = idx & 127;
        Od[((size_t)b * CO + o) * NN + n0 + r] = Sout[o * 132 + r];
    }
}

// ---------------------------------------------------------------------------
// Epilogue: y = wc @ Od + bc -> BN -> ReLU -> out = img + y.  32-wide tiles.
// ---------------------------------------------------------------------------
__global__ void __launch_bounds__(256) out_kernel(
    const float* __restrict__ img, const float* __restrict__ wc,
    const float* __restrict__ bc, const float* __restrict__ gamma,
    const float* __restrict__ beta, const float* __restrict__ mean,
    const float* __restrict__ var, float* __restrict__ out)
{
    extern __shared__ float sm[];
    float* Os = sm;            // [64 o][32 n] = 2048
    float* Ws = sm + 2048;     // [128 c][64 o] = 8192

    int b  = blockIdx.y;
    int n0 = blockIdx.x * 32;
    int tid = threadIdx.x;

    const float* Ob = OdG + (size_t)b * CO * NN;
    for (int idx = tid; idx < 2048; idx += 256) {
        int o = idx >> 5, j = idx & 31;
        Os[idx] = Ob[(size_t)o * NN + n0 + j];
    }
    for (int i = tid; i < 2048; i += 256)
        *(float4*)&Ws[i * 4] = *(const float4*)&wc[i * 4];
    __syncthreads();

    int nx = (tid & 7) * 4;
    int cg = tid >> 3;
    float acc[4][4];
#pragma unroll
    for (int i = 0; i < 4; i++)
#pragma unroll
        for (int j = 0; j < 4; j++) acc[i][j] = 0.f;

#pragma unroll 4
    for (int o = 0; o < CO; o += 2) {
        float4 a0 = *(const float4*)&Os[o * 32 + nx];
        float4 a1 = *(const float4*)&Os[(o + 1) * 32 + nx];
#pragma unroll
        for (int ci = 0; ci < 4; ci++) {
            int c = cg * 4 + ci;
            float2 w2 = *(const float2*)&Ws[c * CO + o];
            acc[ci][0] += w2.x * a0.x + w2.y * a1.x;
            acc[ci][1] += w2.x * a0.y + w2.y * a1.y;
            acc[ci][2] += w2.x * a0.z + w2.y * a1.z;
            acc[ci][3] += w2.x * a0.w + w2.y * a1.w;
        }
    }

#pragma unroll
    for (int ci = 0; ci < 4; ci++) {
        int c = cg * 4 + ci;
        float inv   = gamma[c] * rsqrtf(var[c] + 1e-5f);
        float shift = beta[c] - mean[c] * inv;
        float bias  = bc[c];
        size_t base = (size_t)b * CC * NN + (size_t)c * NN + n0 + nx;
        float4 iv = *(const float4*)&img[base];
        float4 r;
        float y;
        y = (acc[ci][0] + bias) * inv + shift; r.x = iv.x + fmaxf(y, 0.f);
        y = (acc[ci][1] + bias) * inv + shift; r.y = iv.y + fmaxf(y, 0.f);
        y = (acc[ci][2] + bias) * inv + shift; r.z = iv.z + fmaxf(y, 0.f);
        y = (acc[ci][3] + bias) * inv + shift; r.w = iv.w + fmaxf(y, 0.f);
        *(float4*)&out[base] = r;
    }
}

// ---------------------------------------------------------------------------
extern "C" void kernel_launch(void* const* d_in, const int* in_sizes, int n_in,
                              void* d_out, int out_size)
{
    const float* range_x = (const float*)d_in[0];
    const float* img     = (const float*)d_in[1];
    const float* wq      = (const float*)d_in[2];
    const float* bq      = (const float*)d_in[3];
    const float* wk      = (const float*)d_in[4];
    const float* bk      = (const float*)d_in[5];
    const float* wv      = (const float*)d_in[6];
    const float* bv      = (const float*)d_in[7];
    const float* wc      = (const float*)d_in[8];
    const float* bc      = (const float*)d_in[9];
    const float* g       = (const float*)d_in[10];
    const float* be      = (const float*)d_in[11];
    const float* mn      = (const float*)d_in[12];
    const float* vr      = (const float*)d_in[13];
    float* out = (float*)d_out;

    __nv_bfloat16 *qh, *ql, *kh, *kl, *vh, *vl;
    float* od;
    cudaGetSymbolAddress((void**)&qh, QhG);
    cudaGetSymbolAddress((void**)&ql, QlG);
    cudaGetSymbolAddress((void**)&kh, KhG);
    cudaGetSymbolAddress((void**)&kl, KlG);
    cudaGetSymbolAddress((void**)&vh, VhG);
    cudaGetSymbolAddress((void**)&vl, VlG);
    cudaGetSymbolAddress((void**)&od, OdG);

    int smProj = 20480 * sizeof(float);   // 80KB
    int smOut  = 10240 * sizeof(float);   // 40KB

    cudaFuncSetAttribute(proj3_kernel, cudaFuncAttributeMaxDynamicSharedMemorySize, smProj);
    cudaFuncSetAttribute(attn_mma_kernel, cudaFuncAttributeMaxDynamicSharedMemorySize, SMEM_ATTN);
    cudaFuncSetAttribute(out_kernel, cudaFuncAttributeMaxDynamicSharedMemorySize, smOut);

    const float LOG2E = 1.4426950408889634f;
    dim3 gp(NN / 64, BB);    // 256 CTAs

    proj3_kernel<<<gp, 256, smProj>>>(range_x, img, LOG2E,
                                      wq, bq, qh, ql,
                                      wk, bk, kh, kl,
                                      wv, bv, vh, vl);

    dim3 ga(NN / TQ, BB);    // 32 x 4 = 128 CTAs, one per SM
    attn_mma_kernel<<<ga, 256, SMEM_ATTN>>>(od);

    dim3 go(NN / 32, BB);    // 512 CTAs
    out_kernel<<<go, 256, smOut>>>(img, wc, bc, g, be, mn, vr, out);
}